// round 14
// baseline (speedup 1.0000x reference)
#include <cuda_runtime.h>
#include <cuda_bf16.h>
#include <cstdint>

#define KCODES   512
#define DDIM     64
#define HWSZ     4096
#define NPTS     131072
#define TPTS     128
#define NTILES   1024
#define ZQ_ELEMS 8388608
#define NTHREADS 256

#define STRZ     65           // floats per z row (pad -> conflict-free)

// ---- SMEM layout (bytes) ----
// cb frag-major: [64 nblk][4 j][32 lane][8B] = 65536
#define OFF_CB   0
#define OFF_ZF   65536                     // f32 z [128][65]            = 33280
#define OFF_EN   98816                     // f32 ||e||^2 [512]          = 2048
#define OFF_ZN   100864                    // f32 ||z||^2 [128]          = 512
#define OFF_MG   101376                    // f32 margin 2B [128]        = 512
#define OFF_KEY  101888                    // u64 best key [128]         = 1024
#define OFF_IDX  102912                    // i32 idx [128]              = 512
#define OFF_EMX  103424                    // i32 emax bits              = 16
#define SMEM_BYTES 103440

__device__ __forceinline__ void mma16816(float* d, const uint32_t* a,
                                         uint32_t b0, uint32_t b1) {
    asm volatile("mma.sync.aligned.m16n8k16.row.col.f32.bf16.bf16.f32 "
                 "{%0,%1,%2,%3}, {%4,%5,%6,%7}, {%8,%9}, {%0,%1,%2,%3};"
                 : "+f"(d[0]), "+f"(d[1]), "+f"(d[2]), "+f"(d[3])
                 : "r"(a[0]), "r"(a[1]), "r"(a[2]), "r"(a[3]), "r"(b0), "r"(b1));
}
__device__ __forceinline__ uint32_t packbf(float lo, float hi) {
    uint32_t r;
    asm("cvt.rn.bf16x2.f32 %0, %1, %2;" : "=r"(r) : "f"(hi), "f"(lo));
    return r;
}

// exact fp32 rescore: channel-sequential fma chain (same order as proven kernels)
__device__ __forceinline__ void rescore(const float* zf, const float* s_zn,
                                        const float* s_en, unsigned long long* s_key,
                                        const float* cb, int p, int k) {
    const float* er = cb + (size_t)k * DDIM;
    const float* zp = zf + p * STRZ;
    float dot = 0.f;
    #pragma unroll 8
    for (int c = 0; c < DDIM; c++) dot = fmaf(zp[c], __ldg(er + c), dot);
    float dd = s_zn[p] + s_en[k] - 2.f * dot;
    unsigned long long key = ((unsigned long long)__float_as_uint(dd) << 32) | (unsigned)k;
    atomicMin(&s_key[p], key);
}

// 8-code-block batch: 16 rows x 64 cols, K=64. Frag-major LDS.64: coalesced,
// conflict-free, addresses Bbase*1024 + f*1024 + j*256 + lane*8.
__device__ __forceinline__ void run_mma8(float acc[8][4], const uint32_t ra[4][4],
                                         const char* cbb, int Bbase, int lane) {
    #pragma unroll
    for (int f = 0; f < 8; f++)
        #pragma unroll
        for (int e = 0; e < 4; e++) acc[f][e] = 0.f;
    const char* base = cbb + (size_t)Bbase * 1024 + lane * 8;
    #pragma unroll
    for (int j = 0; j < 4; j++) {
        #pragma unroll
        for (int f = 0; f < 8; f++) {
            uint2 bb = *(const uint2*)(base + f * 1024 + j * 256);
            mma16816(acc[f], ra[j], bb.x, bb.y);
        }
    }
}

// mode: 0 = z_q only; 1 = z_q + indices-as-float appended; 2 = indices only
__global__ void __launch_bounds__(NTHREADS, 2)
vq_kernel(const float* __restrict__ z_e,
          const float* __restrict__ cb,
          float* __restrict__ out,
          int mode, int nctas)
{
    extern __shared__ char smem[];
    float* zf    = (float*)(smem + OFF_ZF);
    float* s_en  = (float*)(smem + OFF_EN);
    float* s_zn  = (float*)(smem + OFF_ZN);
    float* s_mg  = (float*)(smem + OFF_MG);
    unsigned long long* s_key = (unsigned long long*)(smem + OFF_KEY);
    int*   s_idx = (int*)(smem + OFF_IDX);
    int*   s_emx = (int*)(smem + OFF_EMX);

    const int tid  = threadIdx.x;
    const int w    = tid >> 5;           // 8 warps
    const int lane = tid & 31;
    const int g    = lane >> 2;
    const int tig  = lane & 3;
    const int m0   = w * 16;             // warp's 16 rows; all 512 codes

    if (tid == 0) *s_emx = 0;
    __syncthreads();

    // ---- Stage codebook once: frag-major bf16 + fp32 ||e||^2 + emax ----
    // code k -> nblk k>>3, col k&7; within 8B: h*4+b*2 <- c = j*16+2*tig+b+8*h
    for (int k = tid; k < KCODES; k += NTHREADS) {
        const float4* e4 = (const float4*)(cb + (size_t)k * DDIM);
        char* base = smem + OFF_CB + (size_t)(k >> 3) * 1024 + (k & 7) * 32;
        float nrm = 0.f, amx = 0.f;
        #pragma unroll
        for (int c4 = 0; c4 < 16; c4++) {
            float4 a = e4[c4];
            float vv[4] = { a.x, a.y, a.z, a.w };
            #pragma unroll
            for (int q = 0; q < 4; q++) {
                int c = 4 * c4 + q;
                float v = vv[q];
                nrm = fmaf(v, v, nrm);
                amx = fmaxf(amx, fabsf(v));
                int j = c >> 4, kk = c & 15;
                int tg = (kk & 7) >> 1, h = kk >> 3, b = kk & 1;
                *(__nv_bfloat16*)(base + j * 256 + tg * 8 + h * 4 + b * 2) =
                    __float2bfloat16(v);
            }
        }
        s_en[k] = nrm;
        atomicMax(s_emx, __float_as_int(amx));
    }
    __syncthreads();
    const float emax = __int_as_float(*s_emx);

    for (int tile = blockIdx.x; tile < NTILES; tile += nctas) {
        __syncthreads();   // prior tile's consumers of zf/s_key/s_idx done

        // ---- Stage z tile fp32 -> zf[p][c] (padded) ----
        {
            const float* zg = z_e + (size_t)(tile >> 5) * (DDIM * HWSZ)
                                  + (size_t)(tile & 31) * TPTS;
            #pragma unroll
            for (int it = 0; it < 8; it++) {
                int i4 = it * NTHREADS + tid;          // 0..2047
                int c = i4 >> 5, p = (i4 & 31) * 4;
                float4 v = *(const float4*)(zg + (size_t)c * HWSZ + p);
                zf[(p + 0) * STRZ + c] = v.x;
                zf[(p + 1) * STRZ + c] = v.y;
                zf[(p + 2) * STRZ + c] = v.z;
                zf[(p + 3) * STRZ + c] = v.w;
            }
        }
        __syncthreads();

        // ---- znorm + margin per point; reset keys (exact-order fma chains) ----
        if (tid < 128) {
            const float* zp = zf + tid * STRZ;
            float zn = 0.f, sab = 0.f;
            #pragma unroll 8
            for (int c = 0; c < DDIM; c++) {
                float v = zp[c];
                zn = fmaf(v, v, zn);
                sab += fabsf(v);
            }
            s_zn[tid] = zn;
            s_mg[tid] = fmaf(0.018f, sab * emax, 1.5e-4f);   // 2B with margin
            s_key[tid] = ~0ull;
        }

        // ---- Register A-fragments (bf16) for this warp's 16 rows ----
        uint32_t ra[4][4];
        #pragma unroll
        for (int j = 0; j < 4; j++) {
            const float* r0 = zf + (m0 + g) * STRZ + 16 * j + 2 * tig;
            const float* r1 = zf + (m0 + g + 8) * STRZ + 16 * j + 2 * tig;
            ra[j][0] = packbf(r0[0], r0[1]);
            ra[j][1] = packbf(r1[0], r1[1]);
            ra[j][2] = packbf(r0[8], r0[9]);
            ra[j][3] = packbf(r1[8], r1[9]);
        }
        __syncthreads();   // s_zn/s_mg/s_key visible to all lanes

        // ---- Single pass: mma sweep + online candidate capture ----
        // Capture rule: t <= runmin + 2B  (k* provably captured by its lane).
        {
            const int pA = m0 + g, pB = m0 + g + 8;
            const float mgA = s_mg[pA], mgB = s_mg[pB];
            float rm0 = 3.402823e38f, rm1 = 3.402823e38f;
            uint32_t cl[8]; int cnt = 0;
            for (int nb = 0; nb < 8; nb++) {
                float acc[8][4];
                run_mma8(acc, ra, smem + OFF_CB, nb * 8, lane);
                #pragma unroll
                for (int f = 0; f < 8; f++) {
                    int k0 = (nb * 8 + f) * 8 + 2 * tig;
                    float e0 = s_en[k0], e1 = s_en[k0 + 1];
                    float t00 = e0 - 2.f * acc[f][0];
                    float t01 = e1 - 2.f * acc[f][1];
                    float t10 = e0 - 2.f * acc[f][2];
                    float t11 = e1 - 2.f * acc[f][3];
                    #pragma unroll
                    for (int e = 0; e < 4; e++) {
                        float t; int p, kk; float mg;
                        if (e == 0)      { t = t00; p = pA; kk = k0;     mg = mgA; }
                        else if (e == 1) { t = t01; p = pA; kk = k0 + 1; mg = mgA; }
                        else if (e == 2) { t = t10; p = pB; kk = k0;     mg = mgB; }
                        else             { t = t11; p = pB; kk = k0 + 1; mg = mgB; }
                        float rm = (p == pA) ? rm0 : rm1;
                        if (t <= rm + mg) {
                            if (cnt < 8) cl[cnt] = ((unsigned)p << 9) | (unsigned)kk;
                            else rescore(zf, s_zn, s_en, s_key, cb, p, kk);
                            cnt++;
                        }
                        if (e < 2) rm0 = fminf(rm0, t); else rm1 = fminf(rm1, t);
                    }
                }
            }
            int nn = cnt < 8 ? cnt : 8;
            for (int i = 0; i < nn; i++)
                rescore(zf, s_zn, s_en, s_key, cb, (int)(cl[i] >> 9), (int)(cl[i] & 511));
        }
        __syncthreads();

        if (tid < 128) s_idx[tid] = (int)(s_key[tid] & 0xFFFFFFFFull);
        __syncthreads();

        // ---- Emit ----
        if (mode == 2) {
            if (tid < 128) ((int*)out)[tile * 128 + tid] = s_idx[tid];
        } else {
            float4* out4 = (float4*)out + (size_t)tile * 2048;
            const float4* cb4 = (const float4*)cb;
            #pragma unroll
            for (int it = 0; it < 8; it++) {
                int i4 = it * NTHREADS + tid;
                int p = i4 >> 4, c4 = i4 & 15;
                out4[i4] = cb4[(size_t)s_idx[p] * 16 + c4];
            }
            if (mode == 1 && tid < 128)
                out[ZQ_ELEMS + tile * 128 + tid] = (float)s_idx[tid];
        }
    }
}

extern "C" void kernel_launch(void* const* d_in, const int* in_sizes, int n_in,
                              void* d_out, int out_size)
{
    const float* z_e = (const float*)d_in[0];
    const float* cb  = (const float*)d_in[1];
    float* out = (float*)d_out;

    int mode;
    if (out_size >= ZQ_ELEMS + NPTS) mode = 1;
    else if (out_size >= ZQ_ELEMS)   mode = 0;
    else                             mode = 2;

    int sms = 0;
    cudaDeviceGetAttribute(&sms, cudaDevAttrMultiProcessorCount, 0);
    if (sms <= 0) sms = 148;
    int nctas = 2 * sms;

    cudaFuncSetAttribute(vq_kernel, cudaFuncAttributeMaxDynamicSharedMemorySize, SMEM_BYTES);
    vq_kernel<<<nctas, NTHREADS, SMEM_BYTES>>>(z_e, cb, out, mode, nctas);
}

// round 16
// speedup vs baseline: 4.4756x; 4.4756x over previous
#include <cuda_runtime.h>
#include <cuda_bf16.h>
#include <cstdint>

#define KCODES   512
#define DDIM     64
#define HWSZ     4096
#define NPTS     131072
#define TPTS     128
#define NTILES   1024
#define ZQ_ELEMS 8388608
#define NTHREADS 256
#define LCAP     256          // per-warp capture list capacity

#define STRZ     65           // floats per z row (pad -> conflict-free)

// ---- SMEM layout (bytes) ----
// cb frag-major: [64 nblk][4 j][32 lane][8B] = 65536
#define OFF_CB   0
#define OFF_ZF   65536                     // f32 z [128][65]            = 33280
#define OFF_EN   98816                     // f32 ||e||^2 [512]          = 2048
#define OFF_ZN   100864                    // f32 ||z||^2 [128]          = 512
#define OFF_MG   101376                    // f32 margin 2B [128]        = 512
#define OFF_KEY  101888                    // u64 best key [128]         = 1024
#define OFF_IDX  102912                    // i32 idx [128]              = 512
#define OFF_EMX  103424                    // i32 emax bits              = 16
#define OFF_CNT  103440                    // i32 capture count [8 warps]= 32
#define OFF_LST  103472                    // u32 list [8][LCAP]         = 8192
#define SMEM_BYTES 111664                  // x2 CTAs = 223328 <= 228KB

__device__ __forceinline__ void mma16816(float* d, const uint32_t* a,
                                         uint32_t b0, uint32_t b1) {
    asm volatile("mma.sync.aligned.m16n8k16.row.col.f32.bf16.bf16.f32 "
                 "{%0,%1,%2,%3}, {%4,%5,%6,%7}, {%8,%9}, {%0,%1,%2,%3};"
                 : "+f"(d[0]), "+f"(d[1]), "+f"(d[2]), "+f"(d[3])
                 : "r"(a[0]), "r"(a[1]), "r"(a[2]), "r"(a[3]), "r"(b0), "r"(b1));
}
__device__ __forceinline__ uint32_t packbf(float lo, float hi) {
    uint32_t r;
    asm("cvt.rn.bf16x2.f32 %0, %1, %2;" : "=r"(r) : "f"(hi), "f"(lo));
    return r;
}

// exact fp32 rescore: channel-sequential fma chain (same order as proven kernels).
// __noinline__: called only after the sweep; keeps the hot loop compact.
__device__ __noinline__ void rescore(const float* zf, const float* s_zn,
                                     const float* s_en, unsigned long long* s_key,
                                     const float* cb, int p, int k) {
    const float* er = cb + (size_t)k * DDIM;
    const float* zp = zf + p * STRZ;
    float dot = 0.f;
    #pragma unroll 8
    for (int c = 0; c < DDIM; c++) dot = fmaf(zp[c], __ldg(er + c), dot);
    float dd = s_zn[p] + s_en[k] - 2.f * dot;
    unsigned long long key = ((unsigned long long)__float_as_uint(dd) << 32) | (unsigned)k;
    atomicMin(&s_key[p], key);
}

// 8-code-block batch: 16 rows x 64 cols, K=64. Frag-major LDS.64: coalesced,
// conflict-free, addresses Bbase*1024 + f*1024 + j*256 + lane*8.
__device__ __forceinline__ void run_mma8(float acc[8][4], const uint32_t ra[4][4],
                                         const char* cbb, int Bbase, int lane) {
    #pragma unroll
    for (int f = 0; f < 8; f++)
        #pragma unroll
        for (int e = 0; e < 4; e++) acc[f][e] = 0.f;
    const char* base = cbb + (size_t)Bbase * 1024 + lane * 8;
    #pragma unroll
    for (int j = 0; j < 4; j++) {
        #pragma unroll
        for (int f = 0; f < 8; f++) {
            uint2 bb = *(const uint2*)(base + f * 1024 + j * 256);
            mma16816(acc[f], ra[j], bb.x, bb.y);
        }
    }
}

// mode: 0 = z_q only; 1 = z_q + indices-as-float appended; 2 = indices only
__global__ void __launch_bounds__(NTHREADS, 2)
vq_kernel(const float* __restrict__ z_e,
          const float* __restrict__ cb,
          float* __restrict__ out,
          int mode, int nctas)
{
    extern __shared__ char smem[];
    float* zf    = (float*)(smem + OFF_ZF);
    float* s_en  = (float*)(smem + OFF_EN);
    float* s_zn  = (float*)(smem + OFF_ZN);
    float* s_mg  = (float*)(smem + OFF_MG);
    unsigned long long* s_key = (unsigned long long*)(smem + OFF_KEY);
    int*   s_idx = (int*)(smem + OFF_IDX);
    int*   s_emx = (int*)(smem + OFF_EMX);
    int*   s_cnt = (int*)(smem + OFF_CNT);
    uint32_t* s_lst = (uint32_t*)(smem + OFF_LST);

    const int tid  = threadIdx.x;
    const int w    = tid >> 5;           // 8 warps
    const int lane = tid & 31;
    const int g    = lane >> 2;
    const int tig  = lane & 3;
    const int m0   = w * 16;             // warp's 16 rows; all 512 codes

    if (tid == 0) *s_emx = 0;
    __syncthreads();

    // ---- Stage codebook once: frag-major bf16 + fp32 ||e||^2 + emax ----
    // code k -> nblk k>>3, col k&7; within 8B: h*4+b*2 <- c = j*16+2*tig+b+8*h
    for (int k = tid; k < KCODES; k += NTHREADS) {
        const float4* e4 = (const float4*)(cb + (size_t)k * DDIM);
        char* base = smem + OFF_CB + (size_t)(k >> 3) * 1024 + (k & 7) * 32;
        float nrm = 0.f, amx = 0.f;
        #pragma unroll
        for (int c4 = 0; c4 < 16; c4++) {
            float4 a = e4[c4];
            float vv[4] = { a.x, a.y, a.z, a.w };
            #pragma unroll
            for (int q = 0; q < 4; q++) {
                int c = 4 * c4 + q;
                float v = vv[q];
                nrm = fmaf(v, v, nrm);
                amx = fmaxf(amx, fabsf(v));
                int j = c >> 4, kk = c & 15;
                int tg = (kk & 7) >> 1, h = kk >> 3, b = kk & 1;
                *(__nv_bfloat16*)(base + j * 256 + tg * 8 + h * 4 + b * 2) =
                    __float2bfloat16(v);
            }
        }
        s_en[k] = nrm;
        atomicMax(s_emx, __float_as_int(amx));
    }
    __syncthreads();
    const float emax = __int_as_float(*s_emx);

    for (int tile = blockIdx.x; tile < NTILES; tile += nctas) {
        __syncthreads();   // prior tile's consumers of zf/s_key/s_idx done

        // ---- Stage z tile fp32 -> zf[p][c] (padded) ----
        {
            const float* zg = z_e + (size_t)(tile >> 5) * (DDIM * HWSZ)
                                  + (size_t)(tile & 31) * TPTS;
            #pragma unroll
            for (int it = 0; it < 8; it++) {
                int i4 = it * NTHREADS + tid;          // 0..2047
                int c = i4 >> 5, p = (i4 & 31) * 4;
                float4 v = *(const float4*)(zg + (size_t)c * HWSZ + p);
                zf[(p + 0) * STRZ + c] = v.x;
                zf[(p + 1) * STRZ + c] = v.y;
                zf[(p + 2) * STRZ + c] = v.z;
                zf[(p + 3) * STRZ + c] = v.w;
            }
        }
        __syncthreads();

        // ---- znorm + margin per point; reset keys/counters ----
        if (tid < 128) {
            const float* zp = zf + tid * STRZ;
            float zn = 0.f, sab = 0.f;
            #pragma unroll 8
            for (int c = 0; c < DDIM; c++) {
                float v = zp[c];
                zn = fmaf(v, v, zn);
                sab += fabsf(v);
            }
            s_zn[tid] = zn;
            s_mg[tid] = fmaf(0.018f, sab * emax, 1.5e-4f);   // 2B with margin
            s_key[tid] = ~0ull;
        }
        if (tid < 8) s_cnt[tid] = 0;

        // ---- Register A-fragments (bf16) for this warp's 16 rows ----
        uint32_t ra[4][4];
        #pragma unroll
        for (int j = 0; j < 4; j++) {
            const float* r0 = zf + (m0 + g) * STRZ + 16 * j + 2 * tig;
            const float* r1 = zf + (m0 + g + 8) * STRZ + 16 * j + 2 * tig;
            ra[j][0] = packbf(r0[0], r0[1]);
            ra[j][1] = packbf(r1[0], r1[1]);
            ra[j][2] = packbf(r0[8], r0[9]);
            ra[j][3] = packbf(r1[8], r1[9]);
        }
        __syncthreads();   // s_zn/s_mg/s_key/s_cnt visible

        // ---- Single sweep with seeded online capture ----
        {
            const int pA = m0 + g, pB = m0 + g + 8;
            const float mgA = s_mg[pA], mgB = s_mg[pB];
            float rm0 = 3.402823e38f, rm1 = 3.402823e38f;

            // Seed: batch 0, min only, then share across the 4 lanes per row
            {
                float acc[8][4];
                run_mma8(acc, ra, smem + OFF_CB, 0, lane);
                #pragma unroll
                for (int f = 0; f < 8; f++) {
                    int k0 = f * 8 + 2 * tig;
                    float e0 = s_en[k0], e1 = s_en[k0 + 1];
                    rm0 = fminf(rm0, fminf(e0 - 2.f * acc[f][0], e1 - 2.f * acc[f][1]));
                    rm1 = fminf(rm1, fminf(e0 - 2.f * acc[f][2], e1 - 2.f * acc[f][3]));
                }
                rm0 = fminf(rm0, __shfl_xor_sync(0xFFFFFFFFu, rm0, 1));
                rm0 = fminf(rm0, __shfl_xor_sync(0xFFFFFFFFu, rm0, 2));
                rm1 = fminf(rm1, __shfl_xor_sync(0xFFFFFFFFu, rm1, 1));
                rm1 = fminf(rm1, __shfl_xor_sync(0xFFFFFFFFu, rm1, 2));
            }

            // Capture sweep: all 8 batches; capture = atomicAdd + 4B store only
            for (int nb = 0; nb < 8; nb++) {
                float acc[8][4];
                run_mma8(acc, ra, smem + OFF_CB, nb * 8, lane);
                #pragma unroll
                for (int f = 0; f < 8; f++) {
                    int k0 = (nb * 8 + f) * 8 + 2 * tig;
                    float e0 = s_en[k0], e1 = s_en[k0 + 1];
                    float t00 = e0 - 2.f * acc[f][0];
                    float t01 = e1 - 2.f * acc[f][1];
                    float t10 = e0 - 2.f * acc[f][2];
                    float t11 = e1 - 2.f * acc[f][3];
                    if (t00 <= rm0 + mgA) {
                        int pos = atomicAdd(&s_cnt[w], 1);
                        if (pos < LCAP) s_lst[w * LCAP + pos] = ((unsigned)pA << 9) | (unsigned)k0;
                    }
                    if (t01 <= rm0 + mgA) {
                        int pos = atomicAdd(&s_cnt[w], 1);
                        if (pos < LCAP) s_lst[w * LCAP + pos] = ((unsigned)pA << 9) | (unsigned)(k0 + 1);
                    }
                    rm0 = fminf(rm0, fminf(t00, t01));
                    if (t10 <= rm1 + mgB) {
                        int pos = atomicAdd(&s_cnt[w], 1);
                        if (pos < LCAP) s_lst[w * LCAP + pos] = ((unsigned)pB << 9) | (unsigned)k0;
                    }
                    if (t11 <= rm1 + mgB) {
                        int pos = atomicAdd(&s_cnt[w], 1);
                        if (pos < LCAP) s_lst[w * LCAP + pos] = ((unsigned)pB << 9) | (unsigned)(k0 + 1);
                    }
                    rm1 = fminf(rm1, fminf(t10, t11));
                }
                // share running min across the 4 lanes covering each row
                rm0 = fminf(rm0, __shfl_xor_sync(0xFFFFFFFFu, rm0, 1));
                rm0 = fminf(rm0, __shfl_xor_sync(0xFFFFFFFFu, rm0, 2));
                rm1 = fminf(rm1, __shfl_xor_sync(0xFFFFFFFFu, rm1, 1));
                rm1 = fminf(rm1, __shfl_xor_sync(0xFFFFFFFFu, rm1, 2));
            }
        }
        __syncwarp();

        // ---- Deferred exact rescores (warp-cooperative) ----
        {
            int total = s_cnt[w];
            if (total <= LCAP) {
                for (int i = lane; i < total; i += 32) {
                    uint32_t en_ = s_lst[w * LCAP + i];
                    rescore(zf, s_zn, s_en, s_key, cb, (int)(en_ >> 9), (int)(en_ & 511));
                }
            } else {
                // overflow (effectively never): exact brute-force for this warp's rows
                for (int r = 0; r < 16; r++)
                    for (int k = lane; k < KCODES; k += 32)
                        rescore(zf, s_zn, s_en, s_key, cb, m0 + r, k);
            }
        }
        __syncthreads();

        if (tid < 128) s_idx[tid] = (int)(s_key[tid] & 0xFFFFFFFFull);
        __syncthreads();

        // ---- Emit ----
        if (mode == 2) {
            if (tid < 128) ((int*)out)[tile * 128 + tid] = s_idx[tid];
        } else {
            float4* out4 = (float4*)out + (size_t)tile * 2048;
            const float4* cb4 = (const float4*)cb;
            #pragma unroll
            for (int it = 0; it < 8; it++) {
                int i4 = it * NTHREADS + tid;
                int p = i4 >> 4, c4 = i4 & 15;
                out4[i4] = cb4[(size_t)s_idx[p] * 16 + c4];
            }
            if (mode == 1 && tid < 128)
                out[ZQ_ELEMS + tile * 128 + tid] = (float)s_idx[tid];
        }
    }
}

extern "C" void kernel_launch(void* const* d_in, const int* in_sizes, int n_in,
                              void* d_out, int out_size)
{
    const float* z_e = (const float*)d_in[0];
    const float* cb  = (const float*)d_in[1];
    float* out = (float*)d_out;

    int mode;
    if (out_size >= ZQ_ELEMS + NPTS) mode = 1;
    else if (out_size >= ZQ_ELEMS)   mode = 0;
    else                             mode = 2;

    int sms = 0;
    cudaDeviceGetAttribute(&sms, cudaDevAttrMultiProcessorCount, 0);
    if (sms <= 0) sms = 148;
    int nctas = 2 * sms;

    cudaFuncSetAttribute(vq_kernel, cudaFuncAttributeMaxDynamicSharedMemorySize, SMEM_BYTES);
    vq_kernel<<<nctas, NTHREADS, SMEM_BYTES>>>(z_e, cb, out, mode, nctas);
}